// round 6
// baseline (speedup 1.0000x reference)
#include <cuda_runtime.h>
#include <cuda_bf16.h>
#include <math.h>
#include <cstdint>

#define NPTS 4096
#define LCH  512
#define ICH  1024
#define HWD  256
#define HEADS 4

// ========================= helpers =========================================
__device__ __forceinline__ uint32_t smem_to_u32(const void* smem_ptr) {
    uint32_t addr;
    asm("{ .reg .u64 tmp; cvta.to.shared.u64 tmp, %1; cvt.u32.u64 %0, tmp; }"
        : "=r"(addr) : "l"(smem_ptr));
    return addr;
}
__device__ __forceinline__ void cp_async16(uint32_t dst_smem, const void* src) {
    asm volatile("cp.async.cg.shared.global [%0], [%1], 16;"
        :: "r"(dst_smem), "l"((unsigned long long)__cvta_generic_to_global(src)) : "memory");
}
#define CP_ASYNC_COMMIT() asm volatile("cp.async.commit_group;" ::: "memory")
#define CP_ASYNC_WAIT(n)  asm volatile("cp.async.wait_group %0;" :: "n"(n) : "memory")

__device__ __forceinline__ void ldsm_x4(uint32_t (&r)[4], uint32_t addr) {
    asm volatile("ldmatrix.sync.aligned.m8n8.x4.shared.b16 {%0,%1,%2,%3}, [%4];"
        : "=r"(r[0]), "=r"(r[1]), "=r"(r[2]), "=r"(r[3]) : "r"(addr));
}
__device__ __forceinline__ void ldsm_x2(uint32_t (&r)[2], uint32_t addr) {
    asm volatile("ldmatrix.sync.aligned.m8n8.x2.shared.b16 {%0,%1}, [%2];"
        : "=r"(r[0]), "=r"(r[1]) : "r"(addr));
}
__device__ __forceinline__ void mma_bf16(float (&d)[4], const uint32_t (&a)[4],
                                         const uint32_t (&b)[2]) {
    asm volatile(
        "mma.sync.aligned.m16n8k16.row.col.f32.bf16.bf16.f32 "
        "{%0,%1,%2,%3}, {%4,%5,%6,%7}, {%8,%9}, {%0,%1,%2,%3};"
        : "+f"(d[0]), "+f"(d[1]), "+f"(d[2]), "+f"(d[3])
        : "r"(a[0]), "r"(a[1]), "r"(a[2]), "r"(a[3]), "r"(b[0]), "r"(b[1]));
}

// ========================= scratch globals =================================
struct PP { int x0, x1, y0, y1; float wa, wb, wc, wd; };
__device__ PP    g_pp[NPTS];
__device__ float g_img [ICH * NPTS];
__device__ float g_Lq  [LCH * NPTS];
__device__ float g_keys[HEADS * LCH * NPTS];
__device__ float g_t   [LCH * NPTS];
__device__ float g_wmap[HEADS * NPTS];

// bf16 split operands (A: [M][K] K-major; BT: [N][K] K-major)
__device__ __nv_bfloat16 g_wK_hi[HEADS * LCH * ICH], g_wK_lo[HEADS * LCH * ICH];
__device__ __nv_bfloat16 g_wL_hi[LCH * LCH],         g_wL_lo[LCH * LCH];
__device__ __nv_bfloat16 g_wF_hi[LCH * LCH],         g_wF_lo[LCH * LCH];
__device__ __nv_bfloat16 g_imgT_hi[NPTS * ICH],      g_imgT_lo[NPTS * ICH];
__device__ __nv_bfloat16 g_pfT_hi [NPTS * LCH],      g_pfT_lo [NPTS * LCH];
__device__ __nv_bfloat16 g_tT_hi  [NPTS * LCH],      g_tT_lo  [NPTS * LCH];

// ========================= small kernels ===================================
__global__ void prep_points(const float* __restrict__ kp) {
    int n = blockIdx.x * blockDim.x + threadIdx.x;
    if (n >= NPTS) return;
    float x = kp[n * 4 + 1] * 256.0f;
    float y = kp[n * 4 + 2] * 256.0f;
    int fx = (int)floorf(x);
    int fy = (int)floorf(y);
    int x0 = min(max(fx,     0), HWD - 1);
    int x1 = min(max(fx + 1, 0), HWD - 1);
    int y0 = min(max(fy,     0), HWD - 1);
    int y1 = min(max(fy + 1, 0), HWD - 1);
    float x0f = (float)x0, x1f = (float)x1, y0f = (float)y0, y1f = (float)y1;
    PP p;
    p.x0 = x0; p.x1 = x1; p.y0 = y0; p.y1 = y1;
    p.wa = (x1f - x) * (y1f - y);
    p.wb = (x1f - x) * (y - y0f);
    p.wc = (x - x0f) * (y1f - y);
    p.wd = (x - x0f) * (y - y0f);
    g_pp[n] = p;
}

__global__ void gather_bev(const float* __restrict__ bev) {
    int n = blockIdx.x * blockDim.x + threadIdx.x;
    int c = blockIdx.y;
    PP p = g_pp[n];
    const float* pl = bev + (size_t)c * (HWD * HWD);
    float v = p.wa * pl[p.y0 * HWD + p.x0]
            + p.wb * pl[p.y1 * HWD + p.x0]
            + p.wc * pl[p.y0 * HWD + p.x1]
            + p.wd * pl[p.y1 * HWD + p.x1];
    g_img[(size_t)c * NPTS + n] = v;
}

// fused split of all three weight tensors (K-major already)
__global__ void cvt_weights(const float* __restrict__ wK, const float* __restrict__ wL,
                            const float* __restrict__ wF) {
    int i = blockIdx.x * blockDim.x + threadIdx.x;
    const int CK = HEADS * LCH * ICH;        // 4194304
    const int CL = LCH * LCH;                // 262144
    const float* src; __nv_bfloat16 *hi, *lo; int j;
    if (i < CK)            { src = wK; hi = g_wK_hi; lo = g_wK_lo; j = i; }
    else if (i < CK + CL)  { src = wL; hi = g_wL_hi; lo = g_wL_lo; j = i - CK; }
    else if (i < CK + 2*CL){ src = wF; hi = g_wF_hi; lo = g_wF_lo; j = i - CK - CL; }
    else return;
    float v = src[j];
    __nv_bfloat16 h = __float2bfloat16(v);
    hi[j] = h;
    lo[j] = __float2bfloat16(v - __bfloat162float(h));
}

// fused transpose+split of pf (K=512) and img (K=1024):
// grid.y in [0,16) -> pf tiles, [16,48) -> img tiles
__global__ __launch_bounds__(256)
void cvt_acts(const float* __restrict__ pf) {
    __shared__ float tile[32][33];
    const float* src; __nv_bfloat16 *hiT, *loT; int K, k0;
    if (blockIdx.y < 16) { src = pf;    hiT = g_pfT_hi;  loT = g_pfT_lo;  K = LCH; k0 = blockIdx.y * 32; }
    else                 { src = g_img; hiT = g_imgT_hi; loT = g_imgT_lo; K = ICH; k0 = (blockIdx.y - 16) * 32; }
    int n0 = blockIdx.x * 32;
    int tx = threadIdx.x & 31;
    int ty = threadIdx.x >> 5;
    #pragma unroll
    for (int j = 0; j < 4; j++) {
        int k = k0 + ty + j * 8;
        tile[ty + j * 8][tx] = src[(size_t)k * NPTS + n0 + tx];
    }
    __syncthreads();
    #pragma unroll
    for (int j = 0; j < 4; j++) {
        int n = n0 + ty + j * 8;
        float v = tile[tx][ty + j * 8];
        __nv_bfloat16 h = __float2bfloat16(v);
        hiT[(size_t)n * K + k0 + tx] = h;
        loT[(size_t)n * K + k0 + tx] = __float2bfloat16(v - __bfloat162float(h));
    }
}

// plain transpose+split (for t)
__global__ __launch_bounds__(256)
void cvt_split_T(const float* __restrict__ src,
                 __nv_bfloat16* __restrict__ hiT,
                 __nv_bfloat16* __restrict__ loT, int K, int N) {
    __shared__ float tile[32][33];
    int n0 = blockIdx.x * 32;
    int k0 = blockIdx.y * 32;
    int tx = threadIdx.x & 31;
    int ty = threadIdx.x >> 5;
    #pragma unroll
    for (int j = 0; j < 4; j++) {
        int k = k0 + ty + j * 8;
        tile[ty + j * 8][tx] = src[(size_t)k * N + n0 + tx];
    }
    __syncthreads();
    #pragma unroll
    for (int j = 0; j < 4; j++) {
        int n = n0 + ty + j * 8;
        float v = tile[tx][ty + j * 8];
        __nv_bfloat16 h = __float2bfloat16(v);
        hiT[(size_t)n * K + k0 + tx] = h;
        loT[(size_t)n * K + k0 + tx] = __float2bfloat16(v - __bfloat162float(h));
    }
}

// ========================= mma.sync split-bf16 GEMM ========================
#define RSB   80
#define TILEB (128 * RSB)
#define STAGEB (4 * TILEB)
#define GEMM_SMEM (2 * STAGEB)        // 81920

__device__ __forceinline__
void gemm_body(const __nv_bfloat16* __restrict__ Ahi,
               const __nv_bfloat16* __restrict__ Alo,
               const __nv_bfloat16* __restrict__ Bhi,
               const __nv_bfloat16* __restrict__ Blo,
               const float* __restrict__ bias,
               float* __restrict__ C, int bm, int bn, int N, int K) {
    extern __shared__ char smem[];
    uint32_t sb = smem_to_u32(smem);

    int tid = threadIdx.x;
    int lane = tid & 31, wid = tid >> 5;
    int warp_m = wid & 1;
    int warp_n = wid >> 1;

    uint32_t aOff[4], bOff[4];
    #pragma unroll
    for (int mi = 0; mi < 4; mi++) {
        int row = warp_m * 64 + mi * 16 + (lane & 15);
        aOff[mi] = (uint32_t)(row * RSB + (lane >> 4) * 16);
    }
    #pragma unroll
    for (int ni = 0; ni < 4; ni++) {
        int row = warp_n * 32 + ni * 8 + (lane & 7);
        bOff[ni] = (uint32_t)(row * RSB + ((lane >> 3) & 1) * 16);
    }

    float acc[4][4][4];
    #pragma unroll
    for (int mi = 0; mi < 4; mi++)
        #pragma unroll
        for (int ni = 0; ni < 4; ni++)
            #pragma unroll
            for (int j = 0; j < 4; j++) acc[mi][ni][j] = 0.0f;

    int ldRow0 = tid >> 2;
    int ldSeg  = tid & 3;
    int nchunks = K >> 5;

    auto load_stage = [&](int stage, int k0) {
        uint32_t s = sb + stage * STAGEB;
        #pragma unroll
        for (int it = 0; it < 2; it++) {
            int row = ldRow0 + it * 64;
            uint32_t so = (uint32_t)(row * RSB + ldSeg * 16);
            size_t goA = (size_t)(bm + row) * K + k0 + ldSeg * 8;
            size_t goB = (size_t)(bn + row) * K + k0 + ldSeg * 8;
            cp_async16(s + 0 * TILEB + so, Ahi + goA);
            cp_async16(s + 1 * TILEB + so, Alo + goA);
            cp_async16(s + 2 * TILEB + so, Bhi + goB);
            cp_async16(s + 3 * TILEB + so, Blo + goB);
        }
    };

    load_stage(0, 0);
    CP_ASYNC_COMMIT();

    for (int c = 0; c < nchunks; c++) {
        if (c + 1 < nchunks) {
            load_stage((c + 1) & 1, (c + 1) << 5);
            CP_ASYNC_COMMIT();
            CP_ASYNC_WAIT(1);
        } else {
            CP_ASYNC_WAIT(0);
        }
        __syncthreads();

        uint32_t s = sb + (c & 1) * STAGEB;
        uint32_t sAh = s, sAl = s + TILEB, sBh = s + 2 * TILEB, sBl = s + 3 * TILEB;

        #pragma unroll
        for (int ks = 0; ks < 2; ks++) {
            uint32_t ko = ks * 32;
            uint32_t a[4][4], bh[4][2], bl[4][2];
            #pragma unroll
            for (int mi = 0; mi < 4; mi++) ldsm_x4(a[mi], sAh + aOff[mi] + ko);
            #pragma unroll
            for (int ni = 0; ni < 4; ni++) ldsm_x2(bh[ni], sBh + bOff[ni] + ko);
            #pragma unroll
            for (int ni = 0; ni < 4; ni++) ldsm_x2(bl[ni], sBl + bOff[ni] + ko);
            #pragma unroll
            for (int mi = 0; mi < 4; mi++)
                #pragma unroll
                for (int ni = 0; ni < 4; ni++) mma_bf16(acc[mi][ni], a[mi], bh[ni]);
            #pragma unroll
            for (int mi = 0; mi < 4; mi++)
                #pragma unroll
                for (int ni = 0; ni < 4; ni++) mma_bf16(acc[mi][ni], a[mi], bl[ni]);
            #pragma unroll
            for (int mi = 0; mi < 4; mi++) ldsm_x4(a[mi], sAl + aOff[mi] + ko);
            #pragma unroll
            for (int mi = 0; mi < 4; mi++)
                #pragma unroll
                for (int ni = 0; ni < 4; ni++) mma_bf16(acc[mi][ni], a[mi], bh[ni]);
        }
        __syncthreads();
    }

    int lr = lane >> 2, lc = (lane & 3) * 2;
    int r0 = bm + warp_m * 64;
    int c0 = bn + warp_n * 32;
    #pragma unroll
    for (int mi = 0; mi < 4; mi++) {
        int m1 = r0 + mi * 16 + lr;
        int m2 = m1 + 8;
        float bv1 = bias[m1];
        float bv2 = bias[m2];
        #pragma unroll
        for (int ni = 0; ni < 4; ni++) {
            int n = c0 + ni * 8 + lc;
            float2 v1 = make_float2(acc[mi][ni][0] + bv1, acc[mi][ni][1] + bv1);
            float2 v2 = make_float2(acc[mi][ni][2] + bv2, acc[mi][ni][3] + bv2);
            *(float2*)(C + (size_t)m1 * N + n) = v1;
            *(float2*)(C + (size_t)m2 * N + n) = v2;
        }
    }
}

// combined launch: blocks [0,512) -> keys GEMM (M=2048,K=1024);
//                  blocks [512,640) -> L_query GEMM (M=512,K=512)
__global__ __launch_bounds__(256, 2)
void gemm_dual(const float* __restrict__ convLb, const float* __restrict__ imgHb) {
    int b = blockIdx.x;
    if (b < 512) {
        int bx = b & 31, by = b >> 5;
        gemm_body(g_wK_hi, g_wK_lo, g_imgT_hi, g_imgT_lo, imgHb, g_keys,
                  by * 128, bx * 128, NPTS, ICH);
    } else {
        int j = b - 512;
        int bx = j & 31, by = j >> 5;
        gemm_body(g_wL_hi, g_wL_lo, g_pfT_hi, g_pfT_lo, convLb, g_Lq,
                  by * 128, bx * 128, NPTS, LCH);
    }
}

__global__ __launch_bounds__(256, 2)
void gemm_single(const __nv_bfloat16* __restrict__ Ahi, const __nv_bfloat16* __restrict__ Alo,
                 const __nv_bfloat16* __restrict__ Bhi, const __nv_bfloat16* __restrict__ Blo,
                 const float* __restrict__ bias, float* __restrict__ C, int N, int K) {
    gemm_body(Ahi, Alo, Bhi, Blo, bias, C, blockIdx.y * 128, blockIdx.x * 128, N, K);
}

// ========================= fused attention tail ============================
// score + softmax + z + t in one kernel (keys 2nd pass hits L2)
__global__ void attn_tail() {
    int n = blockIdx.x * blockDim.x + threadIdx.x;
    float a0 = 0.f, a1 = 0.f, a2 = 0.f, a3 = 0.f;
    for (int l = 0; l < LCH; l++) {
        float lq = g_Lq[l * NPTS + n];
        a0 += g_keys[(0 * LCH + l) * NPTS + n] * lq;
        a1 += g_keys[(1 * LCH + l) * NPTS + n] * lq;
        a2 += g_keys[(2 * LCH + l) * NPTS + n] * lq;
        a3 += g_keys[(3 * LCH + l) * NPTS + n] * lq;
    }
    const float inv = 0.04419417382415922f;  // 1/sqrt(512)
    a0 *= inv; a1 *= inv; a2 *= inv; a3 *= inv;
    float m = fmaxf(fmaxf(a0, a1), fmaxf(a2, a3));
    float e0 = expf(a0 - m), e1 = expf(a1 - m), e2 = expf(a2 - m), e3 = expf(a3 - m);
    float s = e0 + e1 + e2 + e3;
    float w0 = e0 / s, w1 = e1 / s, w2 = e2 / s, w3 = e3 / s;
    g_wmap[0 * NPTS + n] = w0;
    g_wmap[1 * NPTS + n] = w1;
    g_wmap[2 * NPTS + n] = w2;
    g_wmap[3 * NPTS + n] = w3;
    const size_t HS = (size_t)LCH * NPTS;
    for (int l = 0; l < LCH; l++) {
        size_t i = (size_t)l * NPTS + n;
        float z = w0 * g_keys[i] + w1 * g_keys[HS + i]
                + w2 * g_keys[2 * HS + i] + w3 * g_keys[3 * HS + i];
        g_t[i] = z + g_Lq[i];
    }
}

__global__ __launch_bounds__(256)
void layernorm(const float* __restrict__ lnw, const float* __restrict__ lnb) {
    int l = blockIdx.x;
    float* row = g_t + (size_t)l * NPTS;
    float s = 0.f, ss = 0.f;
    for (int n = threadIdx.x; n < NPTS; n += 256) {
        float v = row[n];
        s += v; ss += v * v;
    }
    __shared__ float rs[8], rss[8];
    for (int o = 16; o > 0; o >>= 1) {
        s  += __shfl_down_sync(0xffffffffu, s,  o);
        ss += __shfl_down_sync(0xffffffffu, ss, o);
    }
    int wid = threadIdx.x >> 5, lid = threadIdx.x & 31;
    if (lid == 0) { rs[wid] = s; rss[wid] = ss; }
    __syncthreads();
    if (wid == 0) {
        s  = (lid < 8) ? rs[lid]  : 0.f;
        ss = (lid < 8) ? rss[lid] : 0.f;
        for (int o = 4; o > 0; o >>= 1) {
            s  += __shfl_down_sync(0xffffffffu, s,  o);
            ss += __shfl_down_sync(0xffffffffu, ss, o);
        }
        if (lid == 0) { rs[0] = s; rss[0] = ss; }
    }
    __syncthreads();
    float mu = rs[0] * (1.0f / NPTS);
    float var = rss[0] * (1.0f / NPTS) - mu * mu;
    float rstd = rsqrtf(var + 1e-5f);
    for (int n = threadIdx.x; n < NPTS; n += 256)
        row[n] = (row[n] - mu) * rstd * lnw[n] + lnb[n];
}

__global__ void copy_wmap(float* __restrict__ out) {
    int i = blockIdx.x * blockDim.x + threadIdx.x;
    if (i < HEADS * NPTS) out[i] = g_wmap[i];
}

// ========================= launch ==========================================
extern "C" void kernel_launch(void* const* d_in, const int* in_sizes, int n_in,
                              void* d_out, int out_size) {
    const float* point_features = (const float*)d_in[0];
    const float* keypoints      = (const float*)d_in[1];
    const float* bev_features   = (const float*)d_in[2];
    const float* conv_L_w       = (const float*)d_in[3];
    const float* conv_L_b       = (const float*)d_in[4];
    const float* img_head_w     = (const float*)d_in[5];
    const float* img_head_b     = (const float*)d_in[6];
    const float* ln_w           = (const float*)d_in[7];
    const float* ln_b           = (const float*)d_in[8];
    const float* conv_fusion_w  = (const float*)d_in[9];
    const float* conv_fusion_b  = (const float*)d_in[10];
    float* out = (float*)d_out;

    cudaFuncSetAttribute(gemm_dual,   cudaFuncAttributeMaxDynamicSharedMemorySize, GEMM_SMEM);
    cudaFuncSetAttribute(gemm_single, cudaFuncAttributeMaxDynamicSharedMemorySize, GEMM_SMEM);

    float *p_t;
    cudaGetSymbolAddress((void**)&p_t, g_t);
    __nv_bfloat16 *wFh, *wFl, *tTh, *tTl;
    cudaGetSymbolAddress((void**)&wFh, g_wF_hi);  cudaGetSymbolAddress((void**)&wFl, g_wF_lo);
    cudaGetSymbolAddress((void**)&tTh, g_tT_hi);  cudaGetSymbolAddress((void**)&tTl, g_tT_lo);

    // 1) bilinear params
    prep_points<<<(NPTS + 255) / 256, 256>>>(keypoints);
    // 2) BEV gather
    gather_bev<<<dim3(NPTS / 256, ICH), 256>>>(bev_features);
    // 3) all weight splits (one kernel)
    {
        int count = HEADS * LCH * ICH + 2 * LCH * LCH;
        cvt_weights<<<(count + 255) / 256, 256>>>(img_head_w, conv_L_w, conv_fusion_w);
    }
    // 4) pf + img transpose/split (one kernel)
    cvt_acts<<<dim3(NPTS / 32, 48), 256>>>(point_features);
    // 5) keys GEMM + L_query GEMM in one launch  (profiled slot)
    gemm_dual<<<640, 256, GEMM_SMEM>>>(conv_L_b, img_head_b);
    // 6) fused score/softmax/z/t
    attn_tail<<<NPTS / 256, 256>>>();
    // 7) LayerNorm over point axis
    layernorm<<<LCH, 256>>>(ln_w, ln_b);
    // 8) t transpose/split
    cvt_split_T<<<dim3(NPTS / 32, LCH / 32), 256>>>(p_t, tTh, tTl, LCH, NPTS);
    // 9) fusion GEMM -> out
    gemm_single<<<dim3(NPTS / 128, LCH / 128), 256, GEMM_SMEM>>>(
        wFh, wFl, tTh, tTl, conv_fusion_b, out, NPTS, LCH);
    // 10) weightmap tail
    if (out_size >= LCH * NPTS + HEADS * NPTS) {
        copy_wmap<<<(HEADS * NPTS + 255) / 256, 256>>>(out + (size_t)LCH * NPTS);
    }
}

// round 9
// speedup vs baseline: 1.4773x; 1.4773x over previous
#include <cuda_runtime.h>
#include <cuda_bf16.h>
#include <math.h>
#include <cstdint>

#define NPTS 4096
#define LCH  512
#define ICH  1024
#define HWD  256
#define HEADS 4

// ========================= helpers =========================================
__device__ __forceinline__ uint32_t smem_to_u32(const void* smem_ptr) {
    uint32_t addr;
    asm("{ .reg .u64 tmp; cvta.to.shared.u64 tmp, %1; cvt.u32.u64 %0, tmp; }"
        : "=r"(addr) : "l"(smem_ptr));
    return addr;
}
__device__ __forceinline__ void cp_async16(uint32_t dst_smem, const void* src) {
    asm volatile("cp.async.cg.shared.global [%0], [%1], 16;"
        :: "r"(dst_smem), "l"((unsigned long long)__cvta_generic_to_global(src)) : "memory");
}
#define CP_ASYNC_COMMIT() asm volatile("cp.async.commit_group;" ::: "memory")
#define CP_ASYNC_WAIT(n)  asm volatile("cp.async.wait_group %0;" :: "n"(n) : "memory")

__device__ __forceinline__ void ldsm_x4(uint32_t (&r)[4], uint32_t addr) {
    asm volatile("ldmatrix.sync.aligned.m8n8.x4.shared.b16 {%0,%1,%2,%3}, [%4];"
        : "=r"(r[0]), "=r"(r[1]), "=r"(r[2]), "=r"(r[3]) : "r"(addr));
}
__device__ __forceinline__ void ldsm_x2(uint32_t (&r)[2], uint32_t addr) {
    asm volatile("ldmatrix.sync.aligned.m8n8.x2.shared.b16 {%0,%1}, [%2];"
        : "=r"(r[0]), "=r"(r[1]) : "r"(addr));
}
__device__ __forceinline__ void mma_bf16(float (&d)[4], const uint32_t (&a)[4],
                                         const uint32_t (&b)[2]) {
    asm volatile(
        "mma.sync.aligned.m16n8k16.row.col.f32.bf16.bf16.f32 "
        "{%0,%1,%2,%3}, {%4,%5,%6,%7}, {%8,%9}, {%0,%1,%2,%3};"
        : "+f"(d[0]), "+f"(d[1]), "+f"(d[2]), "+f"(d[3])
        : "r"(a[0]), "r"(a[1]), "r"(a[2]), "r"(a[3]), "r"(b[0]), "r"(b[1]));
}

// ========================= scratch globals =================================
__device__ float g_img [ICH * NPTS];
__device__ float g_Lq  [LCH * NPTS];
__device__ float g_keys[HEADS * LCH * NPTS];
__device__ float g_t   [LCH * NPTS];
__device__ float g_wmap[HEADS * NPTS];
__device__ float g_spart[8][HEADS][NPTS];    // partial scores

__device__ __nv_bfloat16 g_wK_hi[HEADS * LCH * ICH], g_wK_lo[HEADS * LCH * ICH];
__device__ __nv_bfloat16 g_wL_hi[LCH * LCH],         g_wL_lo[LCH * LCH];
__device__ __nv_bfloat16 g_wF_hi[LCH * LCH],         g_wF_lo[LCH * LCH];
__device__ __nv_bfloat16 g_imgT_hi[NPTS * ICH],      g_imgT_lo[NPTS * ICH];
__device__ __nv_bfloat16 g_pfT_hi [NPTS * LCH],      g_pfT_lo [NPTS * LCH];
__device__ __nv_bfloat16 g_tT_hi  [NPTS * LCH],      g_tT_lo  [NPTS * LCH];

// ========================= gather (prep inlined) ===========================
__global__ void gather_bev(const float* __restrict__ bev, const float* __restrict__ kp) {
    int n = blockIdx.x * blockDim.x + threadIdx.x;   // 0..4095
    int c = blockIdx.y;                               // 0..1023
    float x = kp[n * 4 + 1] * 256.0f;
    float y = kp[n * 4 + 2] * 256.0f;
    int fx = (int)floorf(x);
    int fy = (int)floorf(y);
    int x0 = min(max(fx,     0), HWD - 1);
    int x1 = min(max(fx + 1, 0), HWD - 1);
    int y0 = min(max(fy,     0), HWD - 1);
    int y1 = min(max(fy + 1, 0), HWD - 1);
    float x0f = (float)x0, x1f = (float)x1, y0f = (float)y0, y1f = (float)y1;
    float wa = (x1f - x) * (y1f - y);
    float wb = (x1f - x) * (y - y0f);
    float wc = (x - x0f) * (y1f - y);
    float wd = (x - x0f) * (y - y0f);
    const float* pl = bev + (size_t)c * (HWD * HWD);
    float v = wa * pl[y0 * HWD + x0]
            + wb * pl[y1 * HWD + x0]
            + wc * pl[y0 * HWD + x1]
            + wd * pl[y1 * HWD + x1];
    g_img[(size_t)c * NPTS + n] = v;
}

// ========================= converts ========================================
__global__ void cvt_weights(const float* __restrict__ wK, const float* __restrict__ wL,
                            const float* __restrict__ wF) {
    int i = blockIdx.x * blockDim.x + threadIdx.x;
    const int CK = HEADS * LCH * ICH;
    const int CL = LCH * LCH;
    const float* src; __nv_bfloat16 *hi, *lo; int j;
    if (i < CK)            { src = wK; hi = g_wK_hi; lo = g_wK_lo; j = i; }
    else if (i < CK + CL)  { src = wL; hi = g_wL_hi; lo = g_wL_lo; j = i - CK; }
    else if (i < CK + 2*CL){ src = wF; hi = g_wF_hi; lo = g_wF_lo; j = i - CK - CL; }
    else return;
    float v = src[j];
    __nv_bfloat16 h = __float2bfloat16(v);
    hi[j] = h;
    lo[j] = __float2bfloat16(v - __bfloat162float(h));
}

// fused transpose+split of pf (K=512) and img (K=1024)
__global__ __launch_bounds__(256)
void cvt_acts(const float* __restrict__ pf) {
    __shared__ float tile[32][33];
    const float* src; __nv_bfloat16 *hiT, *loT; int K, k0;
    if (blockIdx.y < 16) { src = pf;    hiT = g_pfT_hi;  loT = g_pfT_lo;  K = LCH; k0 = blockIdx.y * 32; }
    else                 { src = g_img; hiT = g_imgT_hi; loT = g_imgT_lo; K = ICH; k0 = (blockIdx.y - 16) * 32; }
    int n0 = blockIdx.x * 32;
    int tx = threadIdx.x & 31;
    int ty = threadIdx.x >> 5;
    #pragma unroll
    for (int j = 0; j < 4; j++) {
        int k = k0 + ty + j * 8;
        tile[ty + j * 8][tx] = src[(size_t)k * NPTS + n0 + tx];
    }
    __syncthreads();
    #pragma unroll
    for (int j = 0; j < 4; j++) {
        int n = n0 + ty + j * 8;
        float v = tile[tx][ty + j * 8];
        __nv_bfloat16 h = __float2bfloat16(v);
        hiT[(size_t)n * K + k0 + tx] = h;
        loT[(size_t)n * K + k0 + tx] = __float2bfloat16(v - __bfloat162float(h));
    }
}

__global__ __launch_bounds__(256)
void cvt_split_T(const float* __restrict__ src,
                 __nv_bfloat16* __restrict__ hiT,
                 __nv_bfloat16* __restrict__ loT, int K, int N) {
    __shared__ float tile[32][33];
    int n0 = blockIdx.x * 32;
    int k0 = blockIdx.y * 32;
    int tx = threadIdx.x & 31;
    int ty = threadIdx.x >> 5;
    #pragma unroll
    for (int j = 0; j < 4; j++) {
        int k = k0 + ty + j * 8;
        tile[ty + j * 8][tx] = src[(size_t)k * N + n0 + tx];
    }
    __syncthreads();
    #pragma unroll
    for (int j = 0; j < 4; j++) {
        int n = n0 + ty + j * 8;
        float v = tile[tx][ty + j * 8];
        __nv_bfloat16 h = __float2bfloat16(v);
        hiT[(size_t)n * K + k0 + tx] = h;
        loT[(size_t)n * K + k0 + tx] = __float2bfloat16(v - __bfloat162float(h));
    }
}

// ========================= mma.sync split-bf16 GEMM ========================
#define RSB   80
#define TILEB (128 * RSB)
#define STAGEB (4 * TILEB)
#define GEMM_SMEM (2 * STAGEB)        // 81920

__global__ __launch_bounds__(256, 2)
void gemm_single(const __nv_bfloat16* __restrict__ Ahi, const __nv_bfloat16* __restrict__ Alo,
                 const __nv_bfloat16* __restrict__ Bhi, const __nv_bfloat16* __restrict__ Blo,
                 const float* __restrict__ bias, float* __restrict__ C, int N, int K) {
    extern __shared__ char smem[];
    uint32_t sb = smem_to_u32(smem);

    int tid = threadIdx.x;
    int lane = tid & 31, wid = tid >> 5;
    int warp_m = wid & 1;
    int warp_n = wid >> 1;
    int bm = blockIdx.y * 128;
    int bn = blockIdx.x * 128;

    uint32_t aOff[4], bOff[4];
    #pragma unroll
    for (int mi = 0; mi < 4; mi++) {
        int row = warp_m * 64 + mi * 16 + (lane & 15);
        aOff[mi] = (uint32_t)(row * RSB + (lane >> 4) * 16);
    }
    #pragma unroll
    for (int ni = 0; ni < 4; ni++) {
        int row = warp_n * 32 + ni * 8 + (lane & 7);
        bOff[ni] = (uint32_t)(row * RSB + ((lane >> 3) & 1) * 16);
    }

    float acc[4][4][4];
    #pragma unroll
    for (int mi = 0; mi < 4; mi++)
        #pragma unroll
        for (int ni = 0; ni < 4; ni++)
            #pragma unroll
            for (int j = 0; j < 4; j++) acc[mi][ni][j] = 0.0f;

    int ldRow0 = tid >> 2;
    int ldSeg  = tid & 3;
    int nchunks = K >> 5;

    auto load_stage = [&](int stage, int k0) {
        uint32_t s = sb + stage * STAGEB;
        #pragma unroll
        for (int it = 0; it < 2; it++) {
            int row = ldRow0 + it * 64;
            uint32_t so = (uint32_t)(row * RSB + ldSeg * 16);
            size_t goA = (size_t)(bm + row) * K + k0 + ldSeg * 8;
            size_t goB = (size_t)(bn + row) * K + k0 + ldSeg * 8;
            cp_async16(s + 0 * TILEB + so, Ahi + goA);
            cp_async16(s + 1 * TILEB + so, Alo + goA);
            cp_async16(s + 2 * TILEB + so, Bhi + goB);
            cp_async16(s + 3 * TILEB + so, Blo + goB);
        }
    };

    load_stage(0, 0);
    CP_ASYNC_COMMIT();

    for (int c = 0; c < nchunks; c++) {
        if (c + 1 < nchunks) {
            load_stage((c + 1) & 1, (c + 1) << 5);
            CP_ASYNC_COMMIT();
            CP_ASYNC_WAIT(1);
        } else {
            CP_ASYNC_WAIT(0);
        }
        __syncthreads();

        uint32_t s = sb + (c & 1) * STAGEB;
        uint32_t sAh = s, sAl = s + TILEB, sBh = s + 2 * TILEB, sBl = s + 3 * TILEB;

        #pragma unroll
        for (int ks = 0; ks < 2; ks++) {
            uint32_t ko = ks * 32;
            uint32_t a[4][4], bh[4][2], bl[4][2];
            #pragma unroll
            for (int mi = 0; mi < 4; mi++) ldsm_x4(a[mi], sAh + aOff[mi] + ko);
            #pragma unroll
            for (int ni = 0; ni < 4; ni++) ldsm_x2(bh[ni], sBh + bOff[ni] + ko);
            #pragma unroll
            for (int ni = 0; ni < 4; ni++) ldsm_x2(bl[ni], sBl + bOff[ni] + ko);
            #pragma unroll
            for (int mi = 0; mi < 4; mi++)
                #pragma unroll
                for (int ni = 0; ni < 4; ni++) mma_bf16(acc[mi][ni], a[mi], bh[ni]);
            #pragma unroll
            for (int mi = 0; mi < 4; mi++)
                #pragma unroll
                for (int ni = 0; ni < 4; ni++) mma_bf16(acc[mi][ni], a[mi], bl[ni]);
            #pragma unroll
            for (int mi = 0; mi < 4; mi++) ldsm_x4(a[mi], sAl + aOff[mi] + ko);
            #pragma unroll
            for (int mi = 0; mi < 4; mi++)
                #pragma unroll
                for (int ni = 0; ni < 4; ni++) mma_bf16(acc[mi][ni], a[mi], bh[ni]);
        }
        __syncthreads();
    }

    int lr = lane >> 2, lc = (lane & 3) * 2;
    int r0 = bm + warp_m * 64;
    int c0 = bn + warp_n * 32;
    #pragma unroll
    for (int mi = 0; mi < 4; mi++) {
        int m1 = r0 + mi * 16 + lr;
        int m2 = m1 + 8;
        float bv1 = bias[m1];
        float bv2 = bias[m2];
        #pragma unroll
        for (int ni = 0; ni < 4; ni++) {
            int n = c0 + ni * 8 + lc;
            float2 v1 = make_float2(acc[mi][ni][0] + bv1, acc[mi][ni][1] + bv1);
            float2 v2 = make_float2(acc[mi][ni][2] + bv2, acc[mi][ni][3] + bv2);
            *(float2*)(C + (size_t)m1 * N + n) = v1;
            *(float2*)(C + (size_t)m2 * N + n) = v2;
        }
    }
}

// ========================= attention tail ==================================
// partial scores: grid (16, 8) — blockIdx.y picks a 64-wide l-chunk
__global__ void score_part() {
    int n = blockIdx.x * blockDim.x + threadIdx.x;
    int l0 = blockIdx.y * 64;
    float a0 = 0.f, a1 = 0.f, a2 = 0.f, a3 = 0.f;
    for (int l = l0; l < l0 + 64; l++) {
        float lq = g_Lq[l * NPTS + n];
        a0 += g_keys[(0 * LCH + l) * NPTS + n] * lq;
        a1 += g_keys[(1 * LCH + l) * NPTS + n] * lq;
        a2 += g_keys[(2 * LCH + l) * NPTS + n] * lq;
        a3 += g_keys[(3 * LCH + l) * NPTS + n] * lq;
    }
    g_spart[blockIdx.y][0][n] = a0;
    g_spart[blockIdx.y][1][n] = a1;
    g_spart[blockIdx.y][2][n] = a2;
    g_spart[blockIdx.y][3][n] = a3;
}

__global__ void softmax_k() {
    int n = blockIdx.x * blockDim.x + threadIdx.x;
    float a0 = 0.f, a1 = 0.f, a2 = 0.f, a3 = 0.f;
    #pragma unroll
    for (int p = 0; p < 8; p++) {
        a0 += g_spart[p][0][n];
        a1 += g_spart[p][1][n];
        a2 += g_spart[p][2][n];
        a3 += g_spart[p][3][n];
    }
    const float inv = 0.04419417382415922f;  // 1/sqrt(512)
    a0 *= inv; a1 *= inv; a2 *= inv; a3 *= inv;
    float m = fmaxf(fmaxf(a0, a1), fmaxf(a2, a3));
    float e0 = expf(a0 - m), e1 = expf(a1 - m), e2 = expf(a2 - m), e3 = expf(a3 - m);
    float s = e0 + e1 + e2 + e3;
    g_wmap[0 * NPTS + n] = e0 / s;
    g_wmap[1 * NPTS + n] = e1 / s;
    g_wmap[2 * NPTS + n] = e2 / s;
    g_wmap[3 * NPTS + n] = e3 / s;
}

__global__ void compute_t() {
    size_t i = (size_t)blockIdx.x * blockDim.x + threadIdx.x;
    int n = (int)(i & (NPTS - 1));
    float w0 = g_wmap[0 * NPTS + n];
    float w1 = g_wmap[1 * NPTS + n];
    float w2 = g_wmap[2 * NPTS + n];
    float w3 = g_wmap[3 * NPTS + n];
    const size_t HS = (size_t)LCH * NPTS;
    float z = w0 * g_keys[i] + w1 * g_keys[HS + i]
            + w2 * g_keys[2 * HS + i] + w3 * g_keys[3 * HS + i];
    g_t[i] = z + g_Lq[i];
}

__global__ __launch_bounds__(256)
void layernorm(const float* __restrict__ lnw, const float* __restrict__ lnb) {
    int l = blockIdx.x;
    float* row = g_t + (size_t)l * NPTS;
    float s = 0.f, ss = 0.f;
    for (int n = threadIdx.x; n < NPTS; n += 256) {
        float v = row[n];
        s += v; ss += v * v;
    }
    __shared__ float rs[8], rss[8];
    for (int o = 16; o > 0; o >>= 1) {
        s  += __shfl_down_sync(0xffffffffu, s,  o);
        ss += __shfl_down_sync(0xffffffffu, ss, o);
    }
    int wid = threadIdx.x >> 5, lid = threadIdx.x & 31;
    if (lid == 0) { rs[wid] = s; rss[wid] = ss; }
    __syncthreads();
    if (wid == 0) {
        s  = (lid < 8) ? rs[lid]  : 0.f;
        ss = (lid < 8) ? rss[lid] : 0.f;
        for (int o = 4; o > 0; o >>= 1) {
            s  += __shfl_down_sync(0xffffffffu, s,  o);
            ss += __shfl_down_sync(0xffffffffu, ss, o);
        }
        if (lid == 0) { rs[0] = s; rss[0] = ss; }
    }
    __syncthreads();
    float mu = rs[0] * (1.0f / NPTS);
    float var = rss[0] * (1.0f / NPTS) - mu * mu;
    float rstd = rsqrtf(var + 1e-5f);
    for (int n = threadIdx.x; n < NPTS; n += 256)
        row[n] = (row[n] - mu) * rstd * lnw[n] + lnb[n];
}

__global__ void copy_wmap(float* __restrict__ out) {
    int i = blockIdx.x * blockDim.x + threadIdx.x;
    if (i < HEADS * NPTS) out[i] = g_wmap[i];
}

// ========================= launch ==========================================
extern "C" void kernel_launch(void* const* d_in, const int* in_sizes, int n_in,
                              void* d_out, int out_size) {
    const float* point_features = (const float*)d_in[0];
    const float* keypoints      = (const float*)d_in[1];
    const float* bev_features   = (const float*)d_in[2];
    const float* conv_L_w       = (const float*)d_in[3];
    const float* conv_L_b       = (const float*)d_in[4];
    const float* img_head_w     = (const float*)d_in[5];
    const float* img_head_b     = (const float*)d_in[6];
    const float* ln_w           = (const float*)d_in[7];
    const float* ln_b           = (const float*)d_in[8];
    const float* conv_fusion_w  = (const float*)d_in[9];
    const float* conv_fusion_b  = (const float*)d_in[10];
    float* out = (float*)d_out;

    cudaFuncSetAttribute(gemm_single, cudaFuncAttributeMaxDynamicSharedMemorySize, GEMM_SMEM);

    float *p_Lq, *p_keys, *p_t;
    cudaGetSymbolAddress((void**)&p_Lq,   g_Lq);
    cudaGetSymbolAddress((void**)&p_keys, g_keys);
    cudaGetSymbolAddress((void**)&p_t,    g_t);
    __nv_bfloat16 *wKh, *wKl, *wLh, *wLl, *wFh, *wFl, *imgTh, *imgTl, *pfTh, *pfTl, *tTh, *tTl;
    cudaGetSymbolAddress((void**)&wKh, g_wK_hi);  cudaGetSymbolAddress((void**)&wKl, g_wK_lo);
    cudaGetSymbolAddress((void**)&wLh, g_wL_hi);  cudaGetSymbolAddress((void**)&wLl, g_wL_lo);
    cudaGetSymbolAddress((void**)&wFh, g_wF_hi);  cudaGetSymbolAddress((void**)&wFl, g_wF_lo);
    cudaGetSymbolAddress((void**)&imgTh, g_imgT_hi); cudaGetSymbolAddress((void**)&imgTl, g_imgT_lo);
    cudaGetSymbolAddress((void**)&pfTh, g_pfT_hi); cudaGetSymbolAddress((void**)&pfTl, g_pfT_lo);
    cudaGetSymbolAddress((void**)&tTh, g_tT_hi);  cudaGetSymbolAddress((void**)&tTl, g_tT_lo);

    // 1) BEV gather (bilinear params inlined)
    gather_bev<<<dim3(NPTS / 256, ICH), 256>>>(bev_features, keypoints);
    // 2) weight splits
    {
        int count = HEADS * LCH * ICH + 2 * LCH * LCH;
        cvt_weights<<<(count + 255) / 256, 256>>>(img_head_w, conv_L_w, conv_fusion_w);
    }
    // 3) pf + img transpose/split
    cvt_acts<<<dim3(NPTS / 32, 48), 256>>>(point_features);
    // 4) keys GEMM  (profiled slot #4)
    gemm_single<<<dim3(NPTS / 128, (HEADS * LCH) / 128), 256, GEMM_SMEM>>>(
        wKh, wKl, imgTh, imgTl, img_head_b, p_keys, NPTS, ICH);
    // 5) L_query GEMM
    gemm_single<<<dim3(NPTS / 128, LCH / 128), 256, GEMM_SMEM>>>(
        wLh, wLl, pfTh, pfTl, conv_L_b, p_Lq, NPTS, LCH);
    // 6) partial scores (128 CTAs)
    score_part<<<dim3(NPTS / 256, 8), 256>>>();
    // 7) softmax over heads
    softmax_k<<<NPTS / 256, 256>>>();
    // 8) t = z + L_query (parallel)
    compute_t<<<(LCH * NPTS) / 256, 256>>>();
    // 9) LayerNorm over point axis
    layernorm<<<LCH, 256>>>(ln_w, ln_b);
    // 10) t transpose/split
    cvt_split_T<<<dim3(NPTS / 32, LCH / 32), 256>>>(p_t, tTh, tTl, LCH, NPTS);
    // 11) fusion GEMM -> out
    gemm_single<<<dim3(NPTS / 128, LCH / 128), 256, GEMM_SMEM>>>(
        wFh, wFl, tTh, tTl, conv_fusion_b, out, NPTS, LCH);
    // 12) weightmap tail
    if (out_size >= LCH * NPTS + HEADS * NPTS) {
        copy_wmap<<<(HEADS * NPTS + 255) / 256, 256>>>(out + (size_t)LCH * NPTS);
    }
}